// round 9
// baseline (speedup 1.0000x reference)
#include <cuda_runtime.h>
#include <cuda_bf16.h>
#include <cstdint>
#include <math.h>

#define DINL __device__ __forceinline__

// ---------------- problem sizes ----------------
constexpr int B_ = 32, S_ = 1024, D_ = 768, HALF = D_ / 2;

// ---------------- scratch (static device globals) ----------------
__device__ __align__(16) __nv_bfloat16 g_xh[B_ * S_ * D_], g_xl[B_ * S_ * D_];
__device__ __align__(16) __nv_bfloat16 g_Wh[3 * D_ * D_], g_Wl[3 * D_ * D_];
__device__ __align__(16) __nv_bfloat16 g_Qh[B_ * S_ * D_], g_Ql[B_ * S_ * D_];
__device__ __align__(16) __nv_bfloat16 g_Kh[B_ * S_ * D_], g_Kl[B_ * S_ * D_];
__device__ __align__(16) __nv_bfloat16 g_Vth[B_ * D_ * S_], g_Vtl[B_ * D_ * S_];
__device__ __align__(16) float g_S[(size_t)B_ * S_ * S_];
__device__ __align__(16) __nv_bfloat16 g_Ph[(size_t)B_ * S_ * S_], g_Pl[(size_t)B_ * S_ * S_];
__device__ float g_cosT[S_ * HALF], g_sinT[S_ * HALF];

// ---------------- tiling ----------------
// CTA tile 128x256, 8 warps of 64x64, K-chunk 32 bf16.
// smem rows: 16 data words + 4 pad = 20 (proven conflict-free pattern).
constexpr int WStr    = 20;
constexpr int ABUF_W  = 128 * WStr;                 // A digit tile: 2560 words
constexpr int BBUF_W  = 256 * WStr;                 // B digit tile: 5120 words
constexpr int STAGE_W = 2 * ABUF_W + 2 * BBUF_W;    // Ah,Al,Bh,Bl = 15360 words
constexpr int SMEM_G  = 2 * STAGE_W * 4;            // double buffer = 122880 B

constexpr int XN4 = (B_ * S_ * D_) / 4;
constexpr int WN4 = (D_ * D_) / 4;

// ---------------- helpers ----------------
DINL uint32_t hi_pack(float a, float b) {  // {bf16_trunc(b), bf16_trunc(a)}, low half = a
    uint32_t r;
    asm("prmt.b32 %0, %1, %2, 0x7632;" : "=r"(r)
        : "r"(__float_as_uint(a)), "r"(__float_as_uint(b)));
    return r;
}

DINL uint32_t lo_pack(float a, float b) {  // rn(residual), low half = a
    float la = a - __uint_as_float(__float_as_uint(a) & 0xffff0000u);
    float lb = b - __uint_as_float(__float_as_uint(b) & 0xffff0000u);
    uint32_t r;
    asm("cvt.rn.bf16x2.f32 %0, %1, %2;" : "=r"(r) : "f"(lb), "f"(la));
    return r;
}

DINL void mma16(float c[4], const uint32_t a[4], const uint32_t b[2]) {
    asm volatile(
        "mma.sync.aligned.m16n8k16.row.col.f32.bf16.bf16.f32 "
        "{%0,%1,%2,%3}, {%4,%5,%6,%7}, {%8,%9}, {%0,%1,%2,%3};\n"
        : "+f"(c[0]), "+f"(c[1]), "+f"(c[2]), "+f"(c[3])
        : "r"(a[0]), "r"(a[1]), "r"(a[2]), "r"(a[3]), "r"(b[0]), "r"(b[1]));
}

// chunk index f -> (row, 16B-chunk); row permutation keeps STS.128 8-lane
// phases on rows (j, j+4): all 32 banks distinct (proven R7/R8).
DINL void chunk_rc(int f, int& row, int& h) {
    int q = f >> 2;
    h = f & 3;
    row = (q & ~7) | ((q & 1) << 2) | ((q >> 1) & 3);
}

// load a digit tile (ROWS x 32 bf16) into NCH uint4 staging regs
template <int ROWS, int NCH, int LDK>
DINL void ldg_tileD(const __nv_bfloat16* __restrict__ g, int kt, uint4 v[NCH], int tid) {
#pragma unroll
    for (int i = 0; i < NCH; i++) {
        int r, h;
        chunk_rc(tid + (i << 8), r, h);
        v[i] = *reinterpret_cast<const uint4*>(g + (size_t)r * LDK + kt * 32 + h * 8);
    }
}

template <int ROWS, int NCH>
DINL void sts_tileD(uint32_t* smw, const uint4 v[NCH], int tid) {
#pragma unroll
    for (int i = 0; i < NCH; i++) {
        int r, h;
        chunk_rc(tid + (i << 8), r, h);
        *reinterpret_cast<uint4*>(smw + r * WStr + h * 4) = v[i];
    }
}

// ---------------- compute one kk half-chunk (K=16) for 64x64 warp tile ----------------
DINL void compute_kk(const uint32_t* __restrict__ sm, int stage, int kk, float c[4][8][4]) {
    const int lane = threadIdx.x & 31, warp = threadIdx.x >> 5;
    const int wm = warp >> 2, wn = warp & 3, g = lane >> 2, tg = lane & 3;
    const uint32_t* Sb = sm + stage * STAGE_W;
    const uint32_t* Ah = Sb;
    const uint32_t* Al = Sb + ABUF_W;
    const uint32_t* Bh = Sb + 2 * ABUF_W;
    const uint32_t* Bl = Sb + 2 * ABUF_W + BBUF_W;

    uint32_t bh[8][2], bl[8][2];
#pragma unroll
    for (int nf = 0; nf < 8; nf++) {
        int o = (wn * 64 + nf * 8 + g) * WStr + kk * 8 + tg;
        bh[nf][0] = Bh[o]; bh[nf][1] = Bh[o + 4];
        bl[nf][0] = Bl[o]; bl[nf][1] = Bl[o + 4];
    }
#pragma unroll
    for (int mf = 0; mf < 4; mf++) {
        int o = (wm * 64 + mf * 16 + g) * WStr + kk * 8 + tg;
        int o8 = o + 8 * WStr;
        uint32_t ah[4] = { Ah[o], Ah[o8], Ah[o + 4], Ah[o8 + 4] };
        uint32_t al[4] = { Al[o], Al[o8], Al[o + 4], Al[o8 + 4] };
        // pass-grouped: accumulator RAW gap = 8 MMAs
#pragma unroll
        for (int nf = 0; nf < 8; nf++) mma16(c[mf][nf], ah, bh[nf]);
#pragma unroll
        for (int nf = 0; nf < 8; nf++) mma16(c[mf][nf], ah, bl[nf]);
#pragma unroll
        for (int nf = 0; nf < 8; nf++) mma16(c[mf][nf], al, bh[nf]);
    }
}

// ---------------- GEMM mainloop: double-buffered, 3-phase staging ----------------
template <int KT, int LDA, int LDB>
DINL void gemm_main(const __nv_bfloat16* __restrict__ Ahg, const __nv_bfloat16* __restrict__ Alg,
                    const __nv_bfloat16* __restrict__ Bhg, const __nv_bfloat16* __restrict__ Blg,
                    uint32_t* sm, float c[4][8][4]) {
    const int tid = threadIdx.x;

#pragma unroll
    for (int mf = 0; mf < 4; mf++)
#pragma unroll
        for (int nf = 0; nf < 8; nf++)
#pragma unroll
            for (int r = 0; r < 4; r++) c[mf][nf][r] = 0.0f;

    {   // prologue: chunk 0 into stage 0 (sequential to keep pressure low)
        uint4 va[2];
        ldg_tileD<128, 2, LDA>(Ahg, 0, va, tid);
        sts_tileD<128, 2>(sm, va, tid);
        ldg_tileD<128, 2, LDA>(Alg, 0, va, tid);
        sts_tileD<128, 2>(sm + ABUF_W, va, tid);
        uint4 vb[4];
        ldg_tileD<256, 4, LDB>(Bhg, 0, vb, tid);
        sts_tileD<256, 4>(sm + 2 * ABUF_W, vb, tid);
        ldg_tileD<256, 4, LDB>(Blg, 0, vb, tid);
        sts_tileD<256, 4>(sm + 2 * ABUF_W + BBUF_W, vb, tid);
    }
    __syncthreads();

    for (int kt = 0; kt < KT; kt++) {
        int stage = kt & 1;
        uint32_t* nsb = sm + (stage ^ 1) * STAGE_W;
        bool more = (kt + 1 < KT);
        {   // phase 1: prefetch Bh while computing kk0
            uint4 sbh[4];
            if (more) ldg_tileD<256, 4, LDB>(Bhg, kt + 1, sbh, tid);
            compute_kk(sm, stage, 0, c);
            if (more) sts_tileD<256, 4>(nsb + 2 * ABUF_W, sbh, tid);
        }
        {   // phase 2: prefetch Bl + A while computing kk1
            uint4 sbl[4], sah[2], sal[2];
            if (more) {
                ldg_tileD<256, 4, LDB>(Blg, kt + 1, sbl, tid);
                ldg_tileD<128, 2, LDA>(Ahg, kt + 1, sah, tid);
                ldg_tileD<128, 2, LDA>(Alg, kt + 1, sal, tid);
            }
            compute_kk(sm, stage, 1, c);
            if (more) {
                sts_tileD<256, 4>(nsb + 2 * ABUF_W + BBUF_W, sbl, tid);
                sts_tileD<128, 2>(nsb, sah, tid);
                sts_tileD<128, 2>(nsb + ABUF_W, sal, tid);
            }
        }
        __syncthreads();
    }
}

// ---------------- kernel 1: all fp32 -> bf16 hi/lo conversions ----------------
__global__ void __launch_bounds__(256)
k_convall(const float* __restrict__ x, const float* __restrict__ Wq,
          const float* __restrict__ Wk, const float* __restrict__ Wv,
          __nv_bfloat16* __restrict__ xh, __nv_bfloat16* __restrict__ xl,
          __nv_bfloat16* __restrict__ wh, __nv_bfloat16* __restrict__ wl) {
    int z = blockIdx.z;
    int i = blockIdx.x * 256 + threadIdx.x;
    const float* src;
    __nv_bfloat16 *dh, *dl;
    int n4;
    if (z == 0) { src = x; dh = xh; dl = xl; n4 = XN4; }
    else {
        src = (z == 1) ? Wq : (z == 2) ? Wk : Wv;
        dh = wh + (size_t)(z - 1) * D_ * D_;
        dl = wl + (size_t)(z - 1) * D_ * D_;
        n4 = WN4;
    }
    if (i >= n4) return;
    float4 v = reinterpret_cast<const float4*>(src)[i];
    uint2 h, l;
    h.x = hi_pack(v.x, v.y); h.y = hi_pack(v.z, v.w);
    l.x = lo_pack(v.x, v.y); l.y = lo_pack(v.z, v.w);
    reinterpret_cast<uint2*>(dh)[i] = h;
    reinterpret_cast<uint2*>(dl)[i] = l;
}

// ---------------- kernel 2: RoPE tables ----------------
__global__ void k_ropetab() {
    int idx = blockIdx.x * 256 + threadIdx.x;
    if (idx >= S_ * HALF) return;
    int s = idx / HALF, i = idx - s * HALF;
    float e = (2.0f * (float)i) / 768.0f;
    float invf = 1.0f / powf(10000.0f, e);
    float ang = (float)s * invf;
    float sn, cs;
    sincosf(ang, &sn, &cs);
    g_cosT[idx] = cs;
    g_sinT[idx] = sn;
}

// ---------------- kernel 3: QKV projection + bias + RoPE -> bf16 hi/lo ----------------
__global__ void __launch_bounds__(256)
k_qkv(const float* __restrict__ bq, const float* __restrict__ bk, const float* __restrict__ bv) {
    extern __shared__ uint32_t sm[];
    int z = blockIdx.z;
    const float* bb = (z == 0) ? bq : (z == 1) ? bk : bv;
    const int bm = blockIdx.y * 128, bn = blockIdx.x * 256;

    float c[4][8][4];
    gemm_main<24, D_, D_>(g_xh + (size_t)bm * D_, g_xl + (size_t)bm * D_,
                          g_Wh + (size_t)z * D_ * D_ + (size_t)bn * D_,
                          g_Wl + (size_t)z * D_ * D_ + (size_t)bn * D_, sm, c);

    const int lane = threadIdx.x & 31, warp = threadIdx.x >> 5;
    const int wm = warp >> 2, wn = warp & 3, g = lane >> 2, tg = lane & 3;
    const float qscale = 0.03608439182435161f;  // 1/sqrt(768)
#pragma unroll
    for (int mf = 0; mf < 4; mf++) {
#pragma unroll
        for (int h = 0; h < 2; h++) {
            int r = bm + wm * 64 + mf * 16 + g + h * 8;
            int s = r & (S_ - 1);
            int b = r >> 10;
#pragma unroll
            for (int nf = 0; nf < 8; nf++) {
                int col = bn + wn * 64 + nf * 8 + 2 * tg;
                float2 bia = *reinterpret_cast<const float2*>(bb + col);
                float v0 = c[mf][nf][h * 2 + 0] + bia.x;
                float v1 = c[mf][nf][h * 2 + 1] + bia.y;
                if (z < 2) {
                    int i = col >> 1;
                    float cs = g_cosT[s * HALF + i];
                    float sn = g_sinT[s * HALF + i];
                    float t0 = v0 * cs - v1 * sn;
                    v1 = v0 * sn + v1 * cs;
                    v0 = t0;
                    if (z == 0) { v0 *= qscale; v1 *= qscale; }
                    __nv_bfloat16* Ch = (z == 0) ? g_Qh : g_Kh;
                    __nv_bfloat16* Cl = (z == 0) ? g_Ql : g_Kl;
                    size_t off = (size_t)r * D_ + col;
                    *reinterpret_cast<uint32_t*>(Ch + off) = hi_pack(v0, v1);
                    *reinterpret_cast<uint32_t*>(Cl + off) = lo_pack(v0, v1);
                } else {
                    size_t boff = (size_t)b * D_ * S_;
                    float h0 = __uint_as_float(__float_as_uint(v0) & 0xffff0000u);
                    float h1 = __uint_as_float(__float_as_uint(v1) & 0xffff0000u);
                    g_Vth[boff + (size_t)col * S_ + s]       = __float2bfloat16(h0);
                    g_Vth[boff + (size_t)(col + 1) * S_ + s] = __float2bfloat16(h1);
                    g_Vtl[boff + (size_t)col * S_ + s]       = __float2bfloat16(v0 - h0);
                    g_Vtl[boff + (size_t)(col + 1) * S_ + s] = __float2bfloat16(v1 - h1);
                }
            }
        }
    }
}

// ---------------- kernel 4: scores = (Q*scale) K^T -> fp32 ----------------
__global__ void __launch_bounds__(256)
k_scores() {
    extern __shared__ uint32_t sm[];
    int z = blockIdx.z;
    const int bm = blockIdx.y * 128, bn = blockIdx.x * 256;
    size_t ao = (size_t)z * S_ * D_ + (size_t)bm * D_;
    size_t bo = (size_t)z * S_ * D_ + (size_t)bn * D_;
    float* C = g_S + (size_t)z * S_ * S_;

    float c[4][8][4];
    gemm_main<24, D_, D_>(g_Qh + ao, g_Ql + ao, g_Kh + bo, g_Kl + bo, sm, c);

    const int lane = threadIdx.x & 31, warp = threadIdx.x >> 5;
    const int wm = warp >> 2, wn = warp & 3, g = lane >> 2, tg = lane & 3;
#pragma unroll
    for (int mf = 0; mf < 4; mf++) {
#pragma unroll
        for (int h = 0; h < 2; h++) {
            int r = bm + wm * 64 + mf * 16 + g + h * 8;
#pragma unroll
            for (int nf = 0; nf < 8; nf++) {
                int col = bn + wn * 64 + nf * 8 + 2 * tg;
                *reinterpret_cast<float2*>(C + (size_t)r * S_ + col) =
                    make_float2(c[mf][nf][h * 2 + 0], c[mf][nf][h * 2 + 1]);
            }
        }
    }
}

// ---------------- kernel 5: row softmax -> bf16 hi/lo P ----------------
__global__ void __launch_bounds__(128)
k_softmax() {
    const float* p = g_S + (size_t)blockIdx.x * S_;
    int t = threadIdx.x;
    float4 a = reinterpret_cast<const float4*>(p)[t];
    float4 b = reinterpret_cast<const float4*>(p)[t + 128];

    float m = fmaxf(fmaxf(fmaxf(a.x, a.y), fmaxf(a.z, a.w)),
                    fmaxf(fmaxf(b.x, b.y), fmaxf(b.z, b.w)));
#pragma unroll
    for (int o = 16; o > 0; o >>= 1) m = fmaxf(m, __shfl_xor_sync(0xffffffffu, m, o));
    __shared__ float r1[4], r2[4];
    if ((t & 31) == 0) r1[t >> 5] = m;
    __syncthreads();
    m = fmaxf(fmaxf(r1[0], r1[1]), fmaxf(r1[2], r1[3]));

    a.x = expf(a.x - m); a.y = expf(a.y - m); a.z = expf(a.z - m); a.w = expf(a.w - m);
    b.x = expf(b.x - m); b.y = expf(b.y - m); b.z = expf(b.z - m); b.w = expf(b.w - m);
    float s = a.x + a.y + a.z + a.w + b.x + b.y + b.z + b.w;
#pragma unroll
    for (int o = 16; o > 0; o >>= 1) s += __shfl_xor_sync(0xffffffffu, s, o);
    if ((t & 31) == 0) r2[t >> 5] = s;
    __syncthreads();
    s = r2[0] + r2[1] + r2[2] + r2[3];
    float inv = 1.0f / s;
    a.x *= inv; a.y *= inv; a.z *= inv; a.w *= inv;
    b.x *= inv; b.y *= inv; b.z *= inv; b.w *= inv;

    uint32_t* ph = reinterpret_cast<uint32_t*>(g_Ph + (size_t)blockIdx.x * S_);
    uint32_t* pl = reinterpret_cast<uint32_t*>(g_Pl + (size_t)blockIdx.x * S_);
    ph[2 * t]       = hi_pack(a.x, a.y);
    ph[2 * t + 1]   = hi_pack(a.z, a.w);
    ph[2 * t + 256] = hi_pack(b.x, b.y);
    ph[2 * t + 257] = hi_pack(b.z, b.w);
    pl[2 * t]       = lo_pack(a.x, a.y);
    pl[2 * t + 1]   = lo_pack(a.z, a.w);
    pl[2 * t + 256] = lo_pack(b.x, b.y);
    pl[2 * t + 257] = lo_pack(b.z, b.w);
}

// ---------------- kernel 6: out = P V (NT via transposed V) ----------------
__global__ void __launch_bounds__(256)
k_pv(float* __restrict__ out) {
    extern __shared__ uint32_t sm[];
    int z = blockIdx.z;
    const int bm = blockIdx.y * 128, bn = blockIdx.x * 256;
    size_t ao = (size_t)z * S_ * S_ + (size_t)bm * S_;
    size_t bo = (size_t)z * D_ * S_ + (size_t)bn * S_;
    float* C = out + (size_t)z * S_ * D_;

    float c[4][8][4];
    gemm_main<32, S_, S_>(g_Ph + ao, g_Pl + ao, g_Vth + bo, g_Vtl + bo, sm, c);

    const int lane = threadIdx.x & 31, warp = threadIdx.x >> 5;
    const int wm = warp >> 2, wn = warp & 3, g = lane >> 2, tg = lane & 3;
#pragma unroll
    for (int mf = 0; mf < 4; mf++) {
#pragma unroll
        for (int h = 0; h < 2; h++) {
            int r = bm + wm * 64 + mf * 16 + g + h * 8;
#pragma unroll
            for (int nf = 0; nf < 8; nf++) {
                int col = bn + wn * 64 + nf * 8 + 2 * tg;
                *reinterpret_cast<float2*>(C + (size_t)r * D_ + col) =
                    make_float2(c[mf][nf][h * 2 + 0], c[mf][nf][h * 2 + 1]);
            }
        }
    }
}

// ---------------- launch ----------------
extern "C" void kernel_launch(void* const* d_in, const int* in_sizes, int n_in,
                              void* d_out, int out_size) {
    const float* x  = (const float*)d_in[0];
    const float* Wq = (const float*)d_in[1];
    const float* bq = (const float*)d_in[2];
    const float* Wk = (const float*)d_in[3];
    const float* bk = (const float*)d_in[4];
    const float* Wv = (const float*)d_in[5];
    const float* bv = (const float*)d_in[6];
    float* out = (float*)d_out;

    cudaFuncSetAttribute(k_qkv,    cudaFuncAttributeMaxDynamicSharedMemorySize, SMEM_G);
    cudaFuncSetAttribute(k_scores, cudaFuncAttributeMaxDynamicSharedMemorySize, SMEM_G);
    cudaFuncSetAttribute(k_pv,     cudaFuncAttributeMaxDynamicSharedMemorySize, SMEM_G);

    void *xh, *xl, *wh, *wl;
    cudaGetSymbolAddress(&xh, g_xh);
    cudaGetSymbolAddress(&xl, g_xl);
    cudaGetSymbolAddress(&wh, g_Wh);
    cudaGetSymbolAddress(&wl, g_Wl);

    // launch order keeps k_scores in the ncu capture slot (4th launch)
    k_convall<<<dim3((XN4 + 255) / 256, 1, 4), 256>>>(
        x, Wq, Wk, Wv,
        (__nv_bfloat16*)xh, (__nv_bfloat16*)xl,
        (__nv_bfloat16*)wh, (__nv_bfloat16*)wl);
    k_ropetab<<<(S_ * HALF + 255) / 256, 256>>>();
    k_qkv<<<dim3(D_ / 256, (B_ * S_) / 128, 3), 256, SMEM_G>>>(bq, bk, bv);
    k_scores<<<dim3(S_ / 256, S_ / 128, B_), 256, SMEM_G>>>();
    k_softmax<<<dim3(B_ * S_), 128>>>();
    k_pv<<<dim3(D_ / 256, S_ / 128, B_), 256, SMEM_G>>>(out);
}

// round 10
// speedup vs baseline: 1.1857x; 1.1857x over previous
#include <cuda_runtime.h>
#include <cuda_fp16.h>
#include <cstdint>
#include <math.h>

#define DINL __device__ __forceinline__

// ---------------- problem sizes ----------------
constexpr int B_ = 32, S_ = 1024, D_ = 768, HALF = D_ / 2;

// ---------------- scratch (static device globals; no allocation) ----------------
__device__ __align__(16) float g_Q[B_ * S_ * D_];
__device__ __align__(16) float g_K[B_ * S_ * D_];
__device__ __align__(16) float g_Vt[B_ * D_ * S_];   // V transposed: [b][d][s]
__device__ __align__(16) float g_S[(size_t)B_ * S_ * S_];
__device__ float g_cosT[S_ * HALF], g_sinT[S_ * HALF];

// ---------------- GEMM tiling (R2-proven) ----------------
// 128x128x32 CTA tile, 8 warps of 64x32, fp16 hi/lo split, mixed-accum 3 passes.
constexpr int BM = 128, BN = 128, BK = 32;
constexpr int WK = BK / 2;              // 16 fp16x2 words per row
constexpr int WStr = WK + 4;            // 20-word padded stride (conflict-free, proven)
constexpr int ABUF_W = BM * WStr;       // 2560 words per buffer
constexpr int SMEM_SZ = 8 * ABUF_W * 4; // Ah,Al,Bh,Bl x double buffer = 81920 B

constexpr float LO_SCALE   = 2048.0f;          // 2^11
constexpr float LO_INV     = 4.8828125e-4f;    // 2^-11

// ---------------- fp16 split helpers ----------------
DINL void split_pack(const float4& v, uint2& h, uint2& l) {
    __half2 h01 = __floats2half2_rn(v.x, v.y);
    __half2 h23 = __floats2half2_rn(v.z, v.w);
    h.x = *reinterpret_cast<const uint32_t*>(&h01);
    h.y = *reinterpret_cast<const uint32_t*>(&h23);
    float l0 = (v.x - __low2float(h01))  * LO_SCALE;
    float l1 = (v.y - __high2float(h01)) * LO_SCALE;
    float l2 = (v.z - __low2float(h23))  * LO_SCALE;
    float l3 = (v.w - __high2float(h23)) * LO_SCALE;
    __half2 l01 = __floats2half2_rn(l0, l1);
    __half2 l23 = __floats2half2_rn(l2, l3);
    l.x = *reinterpret_cast<const uint32_t*>(&l01);
    l.y = *reinterpret_cast<const uint32_t*>(&l23);
}

// f32-accumulator MMA (hi*hi main term)
DINL void mma_f32(float c[4], const uint32_t a[4], const uint32_t b[2]) {
    asm volatile(
        "mma.sync.aligned.m16n8k16.row.col.f32.f16.f16.f32 "
        "{%0,%1,%2,%3}, {%4,%5,%6,%7}, {%8,%9}, {%0,%1,%2,%3};\n"
        : "+f"(c[0]), "+f"(c[1]), "+f"(c[2]), "+f"(c[3])
        : "r"(a[0]), "r"(a[1]), "r"(a[2]), "r"(a[3]), "r"(b[0]), "r"(b[1]));
}

// f16-accumulator MMA (cross terms, scaled by 2^11)
DINL void mma_f16(uint32_t d[2], const uint32_t a[4], const uint32_t b[2]) {
    asm volatile(
        "mma.sync.aligned.m16n8k16.row.col.f16.f16.f16.f16 "
        "{%0,%1}, {%2,%3,%4,%5}, {%6,%7}, {%0,%1};\n"
        : "+r"(d[0]), "+r"(d[1])
        : "r"(a[0]), "r"(a[1]), "r"(a[2]), "r"(a[3]), "r"(b[0]), "r"(b[1]));
}

// combined value: c32 + 2^-11 * c16[r]   (f16-accum reg0 holds c0,c1; reg1 holds c2,c3)
DINL float cval(const float cc[4], const uint32_t ch[2], int r) {
    __half2 p = *reinterpret_cast<const __half2*>(&ch[r >> 1]);
    float corr = (r & 1) ? __high2float(p) : __low2float(p);
    return cc[r] + LO_INV * corr;
}

// ---------------- global -> reg tile loader (128 rows x 32 cols fp32, ld=LD) ----------------
template <int LD>
DINL void ldg_tile(const float* __restrict__ base, int kt, float4* v, int tid) {
#pragma unroll
    for (int i = 0; i < 4; i++) {
        int f = tid + (i << 8);
        int r = f >> 3, c4 = f & 7;
        v[i] = *reinterpret_cast<const float4*>(base + (size_t)r * LD + kt * BK + (c4 << 2));
    }
}

// ---------------- reg -> smem store with fp16 hi/lo split ----------------
DINL void sts_tile(uint32_t* smH, uint32_t* smL, int buf, const float4* v, int tid) {
#pragma unroll
    for (int i = 0; i < 4; i++) {
        int f = tid + (i << 8);
        int r = f >> 3, c4 = f & 7;
        uint2 h, l;
        split_pack(v[i], h, l);
        int off = buf * ABUF_W + r * WStr + (c4 << 1);
        *reinterpret_cast<uint2*>(smH + off) = h;
        *reinterpret_cast<uint2*>(smL + off) = l;
    }
}

// ---------------- compute one 128x128x32 tile (mixed-accum 3 passes) ----------------
DINL void compute_tile(const uint32_t* smAh, const uint32_t* smAl,
                       const uint32_t* smBh, const uint32_t* smBl,
                       int buf, float c[4][4][4], uint32_t ch[4][4][2]) {
    const int lane = threadIdx.x & 31, warp = threadIdx.x >> 5;
    const int wm = warp >> 2, wn = warp & 3, g = lane >> 2, tg = lane & 3;
    const int base = buf * ABUF_W;
#pragma unroll
    for (int kk = 0; kk < 2; kk++) {
        uint32_t bh[4][2], bl[4][2];
#pragma unroll
        for (int nf = 0; nf < 4; nf++) {
            int o = base + (wn * 32 + nf * 8 + g) * WStr + kk * 8 + tg;
            bh[nf][0] = smBh[o]; bh[nf][1] = smBh[o + 4];
            bl[nf][0] = smBl[o]; bl[nf][1] = smBl[o + 4];
        }
#pragma unroll
        for (int mf = 0; mf < 4; mf++) {
            int o = base + (wm * 64 + mf * 16 + g) * WStr + kk * 8 + tg;
            int o8 = o + 8 * WStr;
            uint32_t ah[4] = { smAh[o], smAh[o8], smAh[o + 4], smAh[o8 + 4] };
            uint32_t al[4] = { smAl[o], smAl[o8], smAl[o + 4], smAl[o8 + 4] };
            // pass-grouped: accumulator RAW gap = 4 MMAs per pass
#pragma unroll
            for (int nf = 0; nf < 4; nf++) mma_f32(c[mf][nf], ah, bh[nf]);   // hi*hi (f32 acc)
#pragma unroll
            for (int nf = 0; nf < 4; nf++) mma_f16(ch[mf][nf], ah, bl[nf]);  // hi*lo (f16 acc)
#pragma unroll
            for (int nf = 0; nf < 4; nf++) mma_f16(ch[mf][nf], al, bh[nf]);  // lo*hi (f16 acc)
        }
    }
}

// ---------------- full GEMM mainloop (double-buffered, sync LDG/STS — R2-proven) ----------------
template <int KT, int LDA, int LDB>
DINL void gemm_main(const float* __restrict__ Ab, const float* __restrict__ Bb,
                    uint32_t* sm, float c[4][4][4], uint32_t ch[4][4][2]) {
    const int tid = threadIdx.x;
    uint32_t* Ah = sm;
    uint32_t* Al = sm + 2 * ABUF_W;
    uint32_t* Bh = sm + 4 * ABUF_W;
    uint32_t* Bl = sm + 6 * ABUF_W;

#pragma unroll
    for (int mf = 0; mf < 4; mf++)
#pragma unroll
        for (int nf = 0; nf < 4; nf++) {
#pragma unroll
            for (int r = 0; r < 4; r++) c[mf][nf][r] = 0.0f;
            ch[mf][nf][0] = 0u;
            ch[mf][nf][1] = 0u;
        }

    float4 va[4], vb[4];
    ldg_tile<LDA>(Ab, 0, va, tid);
    ldg_tile<LDB>(Bb, 0, vb, tid);
    sts_tile(Ah, Al, 0, va, tid);
    sts_tile(Bh, Bl, 0, vb, tid);
    __syncthreads();

    for (int kt = 0; kt < KT; kt++) {
        int buf = kt & 1;
        if (kt + 1 < KT) {
            ldg_tile<LDA>(Ab, kt + 1, va, tid);
            ldg_tile<LDB>(Bb, kt + 1, vb, tid);
        }
        compute_tile(Ah, Al, Bh, Bl, buf, c, ch);
        if (kt + 1 < KT) {
            sts_tile(Ah, Al, buf ^ 1, va, tid);
            sts_tile(Bh, Bl, buf ^ 1, vb, tid);
        }
        __syncthreads();
    }
}

// ---------------- kernel 0: RoPE cos/sin tables ----------------
__global__ void k_ropetab() {
    int idx = blockIdx.x * 256 + threadIdx.x;
    if (idx >= S_ * HALF) return;
    int s = idx / HALF, i = idx - s * HALF;
    float e = (2.0f * (float)i) / 768.0f;
    float invf = 1.0f / powf(10000.0f, e);
    float ang = (float)s * invf;
    float sn, cs;
    sincosf(ang, &sn, &cs);
    g_cosT[idx] = cs;
    g_sinT[idx] = sn;
}

// ---------------- kernel 1: QKV projection + bias + RoPE (+scale Q, V transposed) ----------------
__global__ void __launch_bounds__(256, 1)
k_qkv(const float* __restrict__ x,
      const float* __restrict__ Wq, const float* __restrict__ bq,
      const float* __restrict__ Wk, const float* __restrict__ bk,
      const float* __restrict__ Wv, const float* __restrict__ bv) {
    extern __shared__ uint32_t sm[];
    int z = blockIdx.z;
    const float* W  = (z == 0) ? Wq : (z == 1) ? Wk : Wv;
    const float* bb = (z == 0) ? bq : (z == 1) ? bk : bv;

    const int bm = blockIdx.y * BM, bn = blockIdx.x * BN;
    const float* Ab = x + (size_t)bm * D_;
    const float* Bb = W + (size_t)bn * D_;

    float c[4][4][4];
    uint32_t ch[4][4][2];
    gemm_main<24, D_, D_>(Ab, Bb, sm, c, ch);

    const int lane = threadIdx.x & 31, warp = threadIdx.x >> 5;
    const int wm = warp >> 2, wn = warp & 3, g = lane >> 2, tg = lane & 3;
    const float qscale = 0.03608439182435161f;  // 1/sqrt(768)
#pragma unroll
    for (int mf = 0; mf < 4; mf++) {
#pragma unroll
        for (int h = 0; h < 2; h++) {
            int r = bm + wm * 64 + mf * 16 + g + h * 8;
            int s = r & (S_ - 1);
            int b = r >> 10;
#pragma unroll
            for (int nf = 0; nf < 4; nf++) {
                int col = bn + wn * 32 + nf * 8 + 2 * tg;
                float2 bia = *reinterpret_cast<const float2*>(bb + col);
                float v0 = cval(c[mf][nf], ch[mf][nf], h * 2 + 0) + bia.x;
                float v1 = cval(c[mf][nf], ch[mf][nf], h * 2 + 1) + bia.y;
                if (z < 2) {
                    int i = col >> 1;
                    float cs = g_cosT[s * HALF + i];
                    float sn = g_sinT[s * HALF + i];
                    float t0 = v0 * cs - v1 * sn;
                    v1 = v0 * sn + v1 * cs;
                    v0 = t0;
                    if (z == 0) { v0 *= qscale; v1 *= qscale; }
                    float* C = (z == 0) ? g_Q : g_K;
                    *reinterpret_cast<float2*>(C + (size_t)r * D_ + col) = make_float2(v0, v1);
                } else {
                    float* Ct = g_Vt + (size_t)b * D_ * S_;
                    Ct[(size_t)col * S_ + s] = v0;
                    Ct[(size_t)(col + 1) * S_ + s] = v1;
                }
            }
        }
    }
}

// ---------------- kernel 2: scores = (Q*scale) K^T ----------------
__global__ void __launch_bounds__(256, 1)
k_scores() {
    extern __shared__ uint32_t sm[];
    int z = blockIdx.z;
    const int bm = blockIdx.y * BM, bn = blockIdx.x * BN;
    const float* Ab = g_Q + (size_t)z * S_ * D_ + (size_t)bm * D_;
    const float* Bb = g_K + (size_t)z * S_ * D_ + (size_t)bn * D_;
    float* C = g_S + (size_t)z * S_ * S_;

    float c[4][4][4];
    uint32_t ch[4][4][2];
    gemm_main<24, D_, D_>(Ab, Bb, sm, c, ch);

    const int lane = threadIdx.x & 31, warp = threadIdx.x >> 5;
    const int wm = warp >> 2, wn = warp & 3, g = lane >> 2, tg = lane & 3;
#pragma unroll
    for (int mf = 0; mf < 4; mf++) {
#pragma unroll
        for (int h = 0; h < 2; h++) {
            int r = bm + wm * 64 + mf * 16 + g + h * 8;
#pragma unroll
            for (int nf = 0; nf < 4; nf++) {
                int col = bn + wn * 32 + nf * 8 + 2 * tg;
                *reinterpret_cast<float2*>(C + (size_t)r * S_ + col) =
                    make_float2(cval(c[mf][nf], ch[mf][nf], h * 2 + 0),
                                cval(c[mf][nf], ch[mf][nf], h * 2 + 1));
            }
        }
    }
}

// ---------------- kernel 3: row softmax over 1024, in place ----------------
__global__ void __launch_bounds__(128)
k_softmax() {
    float* p = g_S + (size_t)blockIdx.x * S_;
    int t = threadIdx.x;
    float4 a = reinterpret_cast<float4*>(p)[t];
    float4 b = reinterpret_cast<float4*>(p)[t + 128];

    float m = fmaxf(fmaxf(fmaxf(a.x, a.y), fmaxf(a.z, a.w)),
                    fmaxf(fmaxf(b.x, b.y), fmaxf(b.z, b.w)));
#pragma unroll
    for (int o = 16; o > 0; o >>= 1) m = fmaxf(m, __shfl_xor_sync(0xffffffffu, m, o));
    __shared__ float r1[4], r2[4];
    if ((t & 31) == 0) r1[t >> 5] = m;
    __syncthreads();
    m = fmaxf(fmaxf(r1[0], r1[1]), fmaxf(r1[2], r1[3]));

    a.x = expf(a.x - m); a.y = expf(a.y - m); a.z = expf(a.z - m); a.w = expf(a.w - m);
    b.x = expf(b.x - m); b.y = expf(b.y - m); b.z = expf(b.z - m); b.w = expf(b.w - m);
    float s = a.x + a.y + a.z + a.w + b.x + b.y + b.z + b.w;
#pragma unroll
    for (int o = 16; o > 0; o >>= 1) s += __shfl_xor_sync(0xffffffffu, s, o);
    if ((t & 31) == 0) r2[t >> 5] = s;
    __syncthreads();
    s = r2[0] + r2[1] + r2[2] + r2[3];
    float inv = 1.0f / s;
    a.x *= inv; a.y *= inv; a.z *= inv; a.w *= inv;
    b.x *= inv; b.y *= inv; b.z *= inv; b.w *= inv;
    reinterpret_cast<float4*>(p)[t] = a;
    reinterpret_cast<float4*>(p)[t + 128] = b;
}

// ---------------- kernel 4: out = P V (NT via transposed V) ----------------
__global__ void __launch_bounds__(256, 1)
k_pv(float* __restrict__ out) {
    extern __shared__ uint32_t sm[];
    int z = blockIdx.z;
    const int bm = blockIdx.y * BM, bn = blockIdx.x * BN;
    const float* Ab = g_S  + (size_t)z * S_ * S_ + (size_t)bm * S_;
    const float* Bb = g_Vt + (size_t)z * D_ * S_ + (size_t)bn * S_;
    float* C = out + (size_t)z * S_ * D_;

    float c[4][4][4];
    uint32_t ch[4][4][2];
    gemm_main<32, S_, S_>(Ab, Bb, sm, c, ch);

    const int lane = threadIdx.x & 31, warp = threadIdx.x >> 5;
    const int wm = warp >> 2, wn = warp & 3, g = lane >> 2, tg = lane & 3;
#pragma unroll
    for (int mf = 0; mf < 4; mf++) {
#pragma unroll
        for (int h = 0; h < 2; h++) {
            int r = bm + wm * 64 + mf * 16 + g + h * 8;
#pragma unroll
            for (int nf = 0; nf < 4; nf++) {
                int col = bn + wn * 32 + nf * 8 + 2 * tg;
                *reinterpret_cast<float2*>(C + (size_t)r * D_ + col) =
                    make_float2(cval(c[mf][nf], ch[mf][nf], h * 2 + 0),
                                cval(c[mf][nf], ch[mf][nf], h * 2 + 1));
            }
        }
    }
}

// ---------------- launch ----------------
extern "C" void kernel_launch(void* const* d_in, const int* in_sizes, int n_in,
                              void* d_out, int out_size) {
    const float* x  = (const float*)d_in[0];
    const float* Wq = (const float*)d_in[1];
    const float* bq = (const float*)d_in[2];
    const float* Wk = (const float*)d_in[3];
    const float* bk = (const float*)d_in[4];
    const float* Wv = (const float*)d_in[5];
    const float* bv = (const float*)d_in[6];
    float* out = (float*)d_out;

    cudaFuncSetAttribute(k_qkv,    cudaFuncAttributeMaxDynamicSharedMemorySize, SMEM_SZ);
    cudaFuncSetAttribute(k_scores, cudaFuncAttributeMaxDynamicSharedMemorySize, SMEM_SZ);
    cudaFuncSetAttribute(k_pv,     cudaFuncAttributeMaxDynamicSharedMemorySize, SMEM_SZ);

    // ropetab twice (idempotent, ~5us) so the 4th launch — the ncu capture
    // slot — is k_scores.
    k_ropetab<<<(S_ * HALF + 255) / 256, 256>>>();
    k_ropetab<<<(S_ * HALF + 255) / 256, 256>>>();
    k_qkv<<<dim3(D_ / BN, (B_ * S_) / BM, 3), 256, SMEM_SZ>>>(x, Wq, bq, Wk, bk, Wv, bv);
    k_scores<<<dim3(S_ / BN, S_ / BM, B_), 256, SMEM_SZ>>>();
    k_softmax<<<dim3(B_ * S_), 128>>>();
    k_pv<<<dim3(D_ / BN, S_ / BM, B_), 256, SMEM_SZ>>>(out);
}

// round 11
// speedup vs baseline: 1.1859x; 1.0002x over previous
#include <cuda_runtime.h>
#include <cuda_fp16.h>
#include <cstdint>
#include <math.h>

#define DINL __device__ __forceinline__

// ---------------- problem sizes ----------------
constexpr int B_ = 32, S_ = 1024, D_ = 768, HALF = D_ / 2;

// ---------------- scratch (static device globals; no allocation) ----------------
__device__ __align__(16) float g_Q[B_ * S_ * D_];
__device__ __align__(16) float g_K[B_ * S_ * D_];
__device__ __align__(16) float g_Vt[B_ * D_ * S_];   // V transposed: [b][d][s]
__device__ __align__(16) float g_S[(size_t)B_ * S_ * S_];
__device__ float g_cosT[S_ * HALF], g_sinT[S_ * HALF];

// ---------------- GEMM tiling (R2/R10-proven) ----------------
// 128x128x32 CTA tile, 8 warps of 64x32, fp16 hi/lo split, mixed-accum 3 passes.
constexpr int BM = 128, BN = 128, BK = 32;
constexpr int WK = BK / 2;              // 16 fp16x2 words per row
constexpr int WStr = WK + 4;            // 20-word padded stride (conflict-free, proven)
constexpr int ABUF_W = BM * WStr;       // 2560 words per buffer
constexpr int SMEM_SZ = 8 * ABUF_W * 4; // Ah,Al,Bh,Bl x double buffer = 81920 B

constexpr float LO_SCALE = 2048.0f;          // 2^11
constexpr float LO_INV   = 4.8828125e-4f;    // 2^-11

// ---------------- fp16 split helpers ----------------
DINL void split_pack(const float4& v, uint2& h, uint2& l) {
    __half2 h01 = __floats2half2_rn(v.x, v.y);
    __half2 h23 = __floats2half2_rn(v.z, v.w);
    h.x = *reinterpret_cast<const uint32_t*>(&h01);
    h.y = *reinterpret_cast<const uint32_t*>(&h23);
    float l0 = (v.x - __low2float(h01))  * LO_SCALE;
    float l1 = (v.y - __high2float(h01)) * LO_SCALE;
    float l2 = (v.z - __low2float(h23))  * LO_SCALE;
    float l3 = (v.w - __high2float(h23)) * LO_SCALE;
    __half2 l01 = __floats2half2_rn(l0, l1);
    __half2 l23 = __floats2half2_rn(l2, l3);
    l.x = *reinterpret_cast<const uint32_t*>(&l01);
    l.y = *reinterpret_cast<const uint32_t*>(&l23);
}

// f32-accumulator MMA (hi*hi main term)
DINL void mma_f32(float c[4], const uint32_t a[4], const uint32_t b[2]) {
    asm volatile(
        "mma.sync.aligned.m16n8k16.row.col.f32.f16.f16.f32 "
        "{%0,%1,%2,%3}, {%4,%5,%6,%7}, {%8,%9}, {%0,%1,%2,%3};\n"
        : "+f"(c[0]), "+f"(c[1]), "+f"(c[2]), "+f"(c[3])
        : "r"(a[0]), "r"(a[1]), "r"(a[2]), "r"(a[3]), "r"(b[0]), "r"(b[1]));
}

// f16-accumulator MMA (cross terms, scaled by 2^11)
DINL void mma_f16(uint32_t d[2], const uint32_t a[4], const uint32_t b[2]) {
    asm volatile(
        "mma.sync.aligned.m16n8k16.row.col.f16.f16.f16.f16 "
        "{%0,%1}, {%2,%3,%4,%5}, {%6,%7}, {%0,%1};\n"
        : "+r"(d[0]), "+r"(d[1])
        : "r"(a[0]), "r"(a[1]), "r"(a[2]), "r"(a[3]), "r"(b[0]), "r"(b[1]));
}

// combined value: c32 + 2^-11 * c16[r]
DINL float cval(const float cc[4], const uint32_t ch[2], int r) {
    __half2 p = *reinterpret_cast<const __half2*>(&ch[r >> 1]);
    float corr = (r & 1) ? __high2float(p) : __low2float(p);
    return cc[r] + LO_INV * corr;
}

// ---------------- global -> reg tile loader (128 rows x 32 cols fp32, ld=LD) ----------------
template <int LD>
DINL void ldg_tile(const float* __restrict__ base, int kt, float4* v, int tid) {
#pragma unroll
    for (int i = 0; i < 4; i++) {
        int f = tid + (i << 8);
        int r = f >> 3, c4 = f & 7;
        v[i] = *reinterpret_cast<const float4*>(base + (size_t)r * LD + kt * BK + (c4 << 2));
    }
}

// ---------------- reg -> smem store with fp16 hi/lo split ----------------
DINL void sts_tile(uint32_t* smH, uint32_t* smL, int buf, const float4* v, int tid) {
#pragma unroll
    for (int i = 0; i < 4; i++) {
        int f = tid + (i << 8);
        int r = f >> 3, c4 = f & 7;
        uint2 h, l;
        split_pack(v[i], h, l);
        int off = buf * ABUF_W + r * WStr + (c4 << 1);
        *reinterpret_cast<uint2*>(smH + off) = h;
        *reinterpret_cast<uint2*>(smL + off) = l;
    }
}

// ---------------- fragment loaders ----------------
DINL void ld_bfrags(const uint32_t* smBh, const uint32_t* smBl, int base, int kk,
                    int wn, int g, int tg, uint32_t bh[4][2], uint32_t bl[4][2]) {
#pragma unroll
    for (int nf = 0; nf < 4; nf++) {
        int o = base + (wn * 32 + nf * 8 + g) * WStr + kk * 8 + tg;
        bh[nf][0] = smBh[o]; bh[nf][1] = smBh[o + 4];
        bl[nf][0] = smBl[o]; bl[nf][1] = smBl[o + 4];
    }
}

DINL void ld_afrags(const uint32_t* smAh, const uint32_t* smAl, int base, int kk,
                    int mf, int wm, int g, int tg, uint32_t ah[4], uint32_t al[4]) {
    int o = base + (wm * 64 + mf * 16 + g) * WStr + kk * 8 + tg;
    int o8 = o + 8 * WStr;
    ah[0] = smAh[o];     ah[1] = smAh[o8];
    ah[2] = smAh[o + 4]; ah[3] = smAh[o8 + 4];
    al[0] = smAl[o];     al[1] = smAl[o8];
    al[2] = smAl[o + 4]; al[3] = smAl[o8 + 4];
}

// ---------------- full GEMM mainloop: fragment-software-pipelined ----------------
template <int KT, int LDA, int LDB>
DINL void gemm_main(const float* __restrict__ Ab, const float* __restrict__ Bb,
                    uint32_t* sm, float c[4][4][4], uint32_t ch[4][4][2]) {
    const int tid = threadIdx.x;
    const int lane = tid & 31, warp = tid >> 5;
    const int wm = warp >> 2, wn = warp & 3, g = lane >> 2, tg = lane & 3;
    uint32_t* Ah = sm;
    uint32_t* Al = sm + 2 * ABUF_W;
    uint32_t* Bh = sm + 4 * ABUF_W;
    uint32_t* Bl = sm + 6 * ABUF_W;

#pragma unroll
    for (int mf = 0; mf < 4; mf++)
#pragma unroll
        for (int nf = 0; nf < 4; nf++) {
#pragma unroll
            for (int r = 0; r < 4; r++) c[mf][nf][r] = 0.0f;
            ch[mf][nf][0] = 0u;
            ch[mf][nf][1] = 0u;
        }

    float4 va[4], vb[4];
    ldg_tile<LDA>(Ab, 0, va, tid);
    ldg_tile<LDB>(Bb, 0, vb, tid);
    sts_tile(Ah, Al, 0, va, tid);
    sts_tile(Bh, Bl, 0, vb, tid);
    __syncthreads();

    // fragment double-buffers
    uint32_t fbh[2][4][2], fbl[2][4][2];   // B frags per kk
    uint32_t fah[2][4], fal[2][4];         // A frags per (kk,mf) unit, alternating

    for (int kt = 0; kt < KT; kt++) {
        int buf = kt & 1;
        int base = buf * ABUF_W;
        bool more = (kt + 1 < KT);
        if (more) {
            ldg_tile<LDA>(Ab, kt + 1, va, tid);
            ldg_tile<LDB>(Bb, kt + 1, vb, tid);
        }

        // prologue of the chunk: first B-frags and first A-frags
        ld_bfrags(Bh, Bl, base, 0, wn, g, tg, fbh[0], fbl[0]);
        ld_afrags(Ah, Al, base, 0, 0, wm, g, tg, fah[0], fal[0]);

#pragma unroll
        for (int kk = 0; kk < 2; kk++) {
            if (kk == 0)   // prefetch kk=1 B-frags under kk=0 MMAs
                ld_bfrags(Bh, Bl, base, 1, wn, g, tg, fbh[1], fbl[1]);
#pragma unroll
            for (int mf = 0; mf < 4; mf++) {
                const int cur = (kk * 4 + mf) & 1;
                if (!(kk == 1 && mf == 3)) {   // prefetch next unit's A-frags
                    int nkk = (mf == 3) ? 1 : kk;
                    int nmf = (mf + 1) & 3;
                    ld_afrags(Ah, Al, base, nkk, nmf, wm, g, tg, fah[cur ^ 1], fal[cur ^ 1]);
                }
                // pass-grouped MMAs (accumulator RAW gap = 4)
#pragma unroll
                for (int nf = 0; nf < 4; nf++) mma_f32(c[mf][nf], fah[cur], fbh[kk][nf]);
#pragma unroll
                for (int nf = 0; nf < 4; nf++) mma_f16(ch[mf][nf], fah[cur], fbl[kk][nf]);
#pragma unroll
                for (int nf = 0; nf < 4; nf++) mma_f16(ch[mf][nf], fal[cur], fbh[kk][nf]);
            }
        }

        if (more) {
            sts_tile(Ah, Al, buf ^ 1, va, tid);
            sts_tile(Bh, Bl, buf ^ 1, vb, tid);
        }
        __syncthreads();
    }
}

// ---------------- kernel 0: RoPE cos/sin tables ----------------
__global__ void k_ropetab() {
    int idx = blockIdx.x * 256 + threadIdx.x;
    if (idx >= S_ * HALF) return;
    int s = idx / HALF, i = idx - s * HALF;
    float e = (2.0f * (float)i) / 768.0f;
    float invf = 1.0f / powf(10000.0f, e);
    float ang = (float)s * invf;
    float sn, cs;
    sincosf(ang, &sn, &cs);
    g_cosT[idx] = cs;
    g_sinT[idx] = sn;
}

// ---------------- kernel 1: QKV projection + bias + RoPE (+scale Q, V transposed) ----------------
__global__ void __launch_bounds__(256, 1)
k_qkv(const float* __restrict__ x,
      const float* __restrict__ Wq, const float* __restrict__ bq,
      const float* __restrict__ Wk, const float* __restrict__ bk,
      const float* __restrict__ Wv, const float* __restrict__ bv) {
    extern __shared__ uint32_t sm[];
    int z = blockIdx.z;
    const float* W  = (z == 0) ? Wq : (z == 1) ? Wk : Wv;
    const float* bb = (z == 0) ? bq : (z == 1) ? bk : bv;

    const int bm = blockIdx.y * BM, bn = blockIdx.x * BN;
    const float* Ab = x + (size_t)bm * D_;
    const float* Bb = W + (size_t)bn * D_;

    float c[4][4][4];
    uint32_t ch[4][4][2];
    gemm_main<24, D_, D_>(Ab, Bb, sm, c, ch);

    const int lane = threadIdx.x & 31, warp = threadIdx.x >> 5;
    const int wm = warp >> 2, wn = warp & 3, g = lane >> 2, tg = lane & 3;
    const float qscale = 0.03608439182435161f;  // 1/sqrt(768)
#pragma unroll
    for (int mf = 0; mf < 4; mf++) {
#pragma unroll
        for (int h = 0; h < 2; h++) {
            int r = bm + wm * 64 + mf * 16 + g + h * 8;
            int s = r & (S_ - 1);
            int b = r >> 10;
#pragma unroll
            for (int nf = 0; nf < 4; nf++) {
                int col = bn + wn * 32 + nf * 8 + 2 * tg;
                float2 bia = *reinterpret_cast<const float2*>(bb + col);
                float v0 = cval(c[mf][nf], ch[mf][nf], h * 2 + 0) + bia.x;
                float v1 = cval(c[mf][nf], ch[mf][nf], h * 2 + 1) + bia.y;
                if (z < 2) {
                    int i = col >> 1;
                    float cs = g_cosT[s * HALF + i];
                    float sn = g_sinT[s * HALF + i];
                    float t0 = v0 * cs - v1 * sn;
                    v1 = v0 * sn + v1 * cs;
                    v0 = t0;
                    if (z == 0) { v0 *= qscale; v1 *= qscale; }
                    float* C = (z == 0) ? g_Q : g_K;
                    *reinterpret_cast<float2*>(C + (size_t)r * D_ + col) = make_float2(v0, v1);
                } else {
                    float* Ct = g_Vt + (size_t)b * D_ * S_;
                    Ct[(size_t)col * S_ + s] = v0;
                    Ct[(size_t)(col + 1) * S_ + s] = v1;
                }
            }
        }
    }
}

// ---------------- kernel 2: scores = (Q*scale) K^T ----------------
__global__ void __launch_bounds__(256, 1)
k_scores() {
    extern __shared__ uint32_t sm[];
    int z = blockIdx.z;
    const int bm = blockIdx.y * BM, bn = blockIdx.x * BN;
    const float* Ab = g_Q + (size_t)z * S_ * D_ + (size_t)bm * D_;
    const float* Bb = g_K + (size_t)z * S_ * D_ + (size_t)bn * D_;
    float* C = g_S + (size_t)z * S_ * S_;

    float c[4][4][4];
    uint32_t ch[4][4][2];
    gemm_main<24, D_, D_>(Ab, Bb, sm, c, ch);

    const int lane = threadIdx.x & 31, warp = threadIdx.x >> 5;
    const int wm = warp >> 2, wn = warp & 3, g = lane >> 2, tg = lane & 3;
#pragma unroll
    for (int mf = 0; mf < 4; mf++) {
#pragma unroll
        for (int h = 0; h < 2; h++) {
            int r = bm + wm * 64 + mf * 16 + g + h * 8;
#pragma unroll
            for (int nf = 0; nf < 4; nf++) {
                int col = bn + wn * 32 + nf * 8 + 2 * tg;
                *reinterpret_cast<float2*>(C + (size_t)r * S_ + col) =
                    make_float2(cval(c[mf][nf], ch[mf][nf], h * 2 + 0),
                                cval(c[mf][nf], ch[mf][nf], h * 2 + 1));
            }
        }
    }
}

// ---------------- kernel 3: row softmax over 1024, in place ----------------
__global__ void __launch_bounds__(128)
k_softmax() {
    float* p = g_S + (size_t)blockIdx.x * S_;
    int t = threadIdx.x;
    float4 a = reinterpret_cast<float4*>(p)[t];
    float4 b = reinterpret_cast<float4*>(p)[t + 128];

    float m = fmaxf(fmaxf(fmaxf(a.x, a.y), fmaxf(a.z, a.w)),
                    fmaxf(fmaxf(b.x, b.y), fmaxf(b.z, b.w)));
#pragma unroll
    for (int o = 16; o > 0; o >>= 1) m = fmaxf(m, __shfl_xor_sync(0xffffffffu, m, o));
    __shared__ float r1[4], r2[4];
    if ((t & 31) == 0) r1[t >> 5] = m;
    __syncthreads();
    m = fmaxf(fmaxf(r1[0], r1[1]), fmaxf(r1[2], r1[3]));

    a.x = expf(a.x - m); a.y = expf(a.y - m); a.z = expf(a.z - m); a.w = expf(a.w - m);
    b.x = expf(b.x - m); b.y = expf(b.y - m); b.z = expf(b.z - m); b.w = expf(b.w - m);
    float s = a.x + a.y + a.z + a.w + b.x + b.y + b.z + b.w;
#pragma unroll
    for (int o = 16; o > 0; o >>= 1) s += __shfl_xor_sync(0xffffffffu, s, o);
    if ((t & 31) == 0) r2[t >> 5] = s;
    __syncthreads();
    s = r2[0] + r2[1] + r2[2] + r2[3];
    float inv = 1.0f / s;
    a.x *= inv; a.y *= inv; a.z *= inv; a.w *= inv;
    b.x *= inv; b.y *= inv; b.z *= inv; b.w *= inv;
    reinterpret_cast<float4*>(p)[t] = a;
    reinterpret_cast<float4*>(p)[t + 128] = b;
}

// ---------------- kernel 4: out = P V (NT via transposed V) ----------------
__global__ void __launch_bounds__(256, 1)
k_pv(float* __restrict__ out) {
    extern __shared__ uint32_t sm[];
    int z = blockIdx.z;
    const int bm = blockIdx.y * BM, bn = blockIdx.x * BN;
    const float* Ab = g_S  + (size_t)z * S_ * S_ + (size_t)bm * S_;
    const float* Bb = g_Vt + (size_t)z * D_ * S_ + (size_t)bn * S_;
    float* C = out + (size_t)z * S_ * D_;

    float c[4][4][4];
    uint32_t ch[4][4][2];
    gemm_main<32, S_, S_>(Ab, Bb, sm, c, ch);

    const int lane = threadIdx.x & 31, warp = threadIdx.x >> 5;
    const int wm = warp >> 2, wn = warp & 3, g = lane >> 2, tg = lane & 3;
#pragma unroll
    for (int mf = 0; mf < 4; mf++) {
#pragma unroll
        for (int h = 0; h < 2; h++) {
            int r = bm + wm * 64 + mf * 16 + g + h * 8;
#pragma unroll
            for (int nf = 0; nf < 4; nf++) {
                int col = bn + wn * 32 + nf * 8 + 2 * tg;
                *reinterpret_cast<float2*>(C + (size_t)r * D_ + col) =
                    make_float2(cval(c[mf][nf], ch[mf][nf], h * 2 + 0),
                                cval(c[mf][nf], ch[mf][nf], h * 2 + 1));
            }
        }
    }
}

// ---------------- launch ----------------
extern "C" void kernel_launch(void* const* d_in, const int* in_sizes, int n_in,
                              void* d_out, int out_size) {
    const float* x  = (const float*)d_in[0];
    const float* Wq = (const float*)d_in[1];
    const float* bq = (const float*)d_in[2];
    const float* Wk = (const float*)d_in[3];
    const float* bk = (const float*)d_in[4];
    const float* Wv = (const float*)d_in[5];
    const float* bv = (const float*)d_in[6];
    float* out = (float*)d_out;

    cudaFuncSetAttribute(k_qkv,    cudaFuncAttributeMaxDynamicSharedMemorySize, SMEM_SZ);
    cudaFuncSetAttribute(k_scores, cudaFuncAttributeMaxDynamicSharedMemorySize, SMEM_SZ);
    cudaFuncSetAttribute(k_pv,     cudaFuncAttributeMaxDynamicSharedMemorySize, SMEM_SZ);

    // ropetab twice (idempotent, ~5us) so the 4th launch — the ncu capture
    // slot — is k_scores.
    k_ropetab<<<(S_ * HALF + 255) / 256, 256>>>();
    k_ropetab<<<(S_ * HALF + 255) / 256, 256>>>();
    k_qkv<<<dim3(D_ / BN, (B_ * S_) / BM, 3), 256, SMEM_SZ>>>(x, Wq, bq, Wk, bk, Wv, bv);
    k_scores<<<dim3(S_ / BN, S_ / BM, B_), 256, SMEM_SZ>>>();
    k_softmax<<<dim3(B_ * S_), 128>>>();
    k_pv<<<dim3(D_ / BN, S_ / BM, B_), 256, SMEM_SZ>>>(out);
}